// round 7
// baseline (speedup 1.0000x reference)
#include <cuda_runtime.h>
#include <math.h>

// DCN collapsed-affine, round 7:
//  - chain unchanged from R6 (v3 / v2 / u+atomics, ~3us)
//  - k_main: 512 thr (16 warps, 1 row/warp), grid 256, 2 blocks/SM,
//    depth-13 register prefetch pipeline for the embedding gather.

#define EPSF 1e-5f

constexpr int Bn   = 4096;
constexpr int Fn   = 26;
constexpr int Vn   = 10000;
constexpr int Dn   = 64;
constexpr int D0   = 1664;   // Fn*Dn
constexpr int NUMB = 13;
constexpr int INW  = 1677;   // D0 + NUMB
constexpr int H1   = 1024;
constexpr int H2   = 512;
constexpr int H3   = 256;

// Scratch (device globals)
__device__ float g_v3p[16][H2];
__device__ float g_v2p[16][H1];
__device__ float g_u[1792];
__device__ float g_r;

__device__ __forceinline__ float warp_sum(float v) {
    #pragma unroll
    for (int o = 16; o; o >>= 1) v += __shfl_xor_sync(0xffffffffu, v, o);
    return v;
}

// ---------------------------------------------------------------------------
__global__ __launch_bounds__(256) void k_v3(
    const float* __restrict__ w3, const float* __restrict__ bn3,
    const float* __restrict__ pred_w, const float* __restrict__ pred_b) {
    int bid = blockIdx.x;
    int ib = bid >> 1, jb = bid & 1;
    int t = threadIdx.x;
    int i0 = ib * 16;
    __shared__ float ts[16];
    if (t < 16) {
        int i = i0 + t;
        float a3 = bn3[i] * rsqrtf(bn3[3 * H3 + i] + EPSF);
        ts[t] = a3 * pred_w[D0 + i];
    }
    int gt = bid * 256 + t;
    if (gt < 1792) g_u[gt] = 0.f;
    if (gt == 0) g_r = pred_b[0];
    __syncthreads();
    int j = jb * 256 + t;
    float acc = 0.f;
    #pragma unroll
    for (int i = 0; i < 16; i++) acc += w3[(i0 + i) * H2 + j] * ts[i];
    g_v3p[ib][j] = acc;
}

// ---------------------------------------------------------------------------
__global__ __launch_bounds__(128) void k_v2(
    const float* __restrict__ w2, const float* __restrict__ bn2,
    const float* __restrict__ b2, const float* __restrict__ bn3,
    const float* __restrict__ b3, const float* __restrict__ pred_w) {
    int bid = blockIdx.x;
    int jb = bid & 7, ib = bid >> 3;
    int t = threadIdx.x;
    int i0 = ib * 32;
    __shared__ float ts[32];
    __shared__ float red[4];
    float rloc = 0.f;

    if (t < 32) {
        int i = i0 + t;
        float v3 = 0.f;
        #pragma unroll
        for (int p = 0; p < 16; p++) v3 += g_v3p[p][i];
        float a2 = bn2[i] * rsqrtf(bn2[3 * H2 + i] + EPSF);
        ts[t] = a2 * v3;
        if (jb == 0)
            rloc += (a2 * b2[i] + bn2[H2 + i] - bn2[2 * H2 + i] * a2) * v3;
    }
    if (bid == 0) {
        #pragma unroll
        for (int i = t; i < H3; i += 128) {
            float a3 = bn3[i] * rsqrtf(bn3[3 * H3 + i] + EPSF);
            rloc += (a3 * b3[i] + bn3[H3 + i] - bn3[2 * H3 + i] * a3) * pred_w[D0 + i];
        }
    }
    __syncthreads();

    int j = jb * 128 + t;
    float acc = 0.f;
    #pragma unroll 8
    for (int i = 0; i < 32; i++) acc += w2[(i0 + i) * H1 + j] * ts[i];
    g_v2p[ib][j] = acc;

    if (jb == 0) {
        rloc = warp_sum(rloc);
        if ((t & 31) == 0) red[t >> 5] = rloc;
        __syncthreads();
        if (t == 0) atomicAdd(&g_r, red[0] + red[1] + red[2] + red[3]);
    }
}

// ---------------------------------------------------------------------------
__global__ __launch_bounds__(256) void k_u(
    const float* __restrict__ w1, const float* __restrict__ bn1,
    const float* __restrict__ b1, const float* __restrict__ bn0) {
    int bid = blockIdx.x;
    int jb = bid % 7, ib = bid / 7;
    int t = threadIdx.x;
    int i0 = ib * 64;
    __shared__ float ts[64];
    __shared__ float red[8];
    float rloc = 0.f;

    if (t < 64) {
        int i = i0 + t;
        float v2 = 0.f;
        #pragma unroll
        for (int p = 0; p < 16; p++) v2 += g_v2p[p][i];
        float a1 = bn1[i] * rsqrtf(bn1[3 * H1 + i] + EPSF);
        ts[t] = a1 * v2;
        if (jb == 0)
            rloc += (a1 * b1[i] + bn1[H1 + i] - bn1[2 * H1 + i] * a1) * v2;
    }
    __syncthreads();

    int j = jb * 256 + t;
    if (j < INW) {
        float acc = 0.f;
        #pragma unroll 16
        for (int i = 0; i < 64; i++)
            acc += w1[(size_t)(i0 + i) * INW + j] * ts[i];
        atomicAdd(&g_u[j], acc);
        float a0 = bn0[j] * rsqrtf(bn0[3 * INW + j] + EPSF);
        float c0 = bn0[INW + j] - bn0[2 * INW + j] * a0;
        rloc += c0 * acc;
    }

    rloc = warp_sum(rloc);
    if ((t & 31) == 0) red[t >> 5] = rloc;
    __syncthreads();
    if (t == 0) {
        float rb = 0.f;
        #pragma unroll
        for (int w = 0; w < 8; w++) rb += red[w];
        atomicAdd(&g_r, rb);
    }
}

// ---------------------------------------------------------------------------
// Main gather kernel: 512 thr (16 warps, 1 row/warp), grid 256, 2 blocks/SM.
// Depth-13 register prefetch: 13 independent gather loads always in flight.
__global__ __launch_bounds__(512, 2) void k_main(
    const float* __restrict__ numb, const int* __restrict__ cat,
    const float* __restrict__ emb,  const float* __restrict__ cross_w,
    const float* __restrict__ cross_b, const float* __restrict__ pred_w,
    const float* __restrict__ bn0, float* __restrict__ out) {

    __shared__ float2 sv0[832], sv1[832], sv2[832], sv3[832], sv4[832];
    __shared__ float  s_qn[16];
    __shared__ float  redm[3][16];
    __shared__ float  s_sc[4];

    const int tid  = threadIdx.x;
    const int warp = tid >> 5;
    const int lane = tid & 31;
    const int row  = blockIdx.x * 16 + warp;

    int mi = (lane < Fn) ? cat[row * Fn + lane] : 0;

    // ---- prologue: staging, q from g_u, Sc sums ----
    float p1 = 0.f, p2 = 0.f, p3 = 0.f;
    {
        const float2* cwp = (const float2*)cross_w;
        const float2* pwp = (const float2*)pred_w;
        #pragma unroll
        for (int k = tid; k < 832; k += 512) {
            float2 c0 = cwp[k];
            float2 c1 = cwp[832 + k];
            float2 c2 = cwp[1664 + k];
            float2 pw = pwp[k];
            sv0[k] = c0; sv1[k] = c1; sv2[k] = c2; sv3[k] = pw;
            p1 += c1.x + c1.y; p2 += c2.x + c2.y; p3 += pw.x + pw.y;
        }
        float* sv4f = (float*)sv4;
        #pragma unroll
        for (int j = tid; j < INW; j += 512) {
            float a0 = bn0[j] * rsqrtf(bn0[3 * INW + j] + EPSF);
            float q = a0 * g_u[j];
            if (j < D0) sv4f[j] = q;
            else        s_qn[j - D0] = q;
        }
        if (tid == 0) s_sc[3] = g_r;
    }
    p1 = warp_sum(p1); p2 = warp_sum(p2); p3 = warp_sum(p3);
    if (lane == 0) { redm[0][warp] = p1; redm[1][warp] = p2; redm[2][warp] = p3; }
    __syncthreads();
    if (tid < 32) {
        float a = (tid < 16) ? redm[0][tid] : 0.f;
        float b = (tid < 16) ? redm[1][tid] : 0.f;
        float c = (tid < 16) ? redm[2][tid] : 0.f;
        a = warp_sum(a); b = warp_sum(b); c = warp_sum(c);
        if (tid == 0) { s_sc[0] = a; s_sc[1] = b; s_sc[2] = c; }
    }
    __syncthreads();

    // ---- gather: depth-13 register pipeline ----
    float acc0 = 0.f, acc1 = 0.f, acc2 = 0.f, acc3 = 0.f, acc4 = 0.f;
    float2 e[13];

    #define EMB_LD(F) \
        __ldg(reinterpret_cast<const float2*>(emb + (size_t)(F) * (Vn * Dn)) \
              + (size_t)__shfl_sync(0xffffffffu, mi, (F)) * 32 + lane)

    #pragma unroll
    for (int ff = 0; ff < 13; ff++) e[ff] = EMB_LD(ff);

    #pragma unroll
    for (int f = 0; f < Fn; f++) {
        float2 ev = e[f % 13];
        if (f + 13 < Fn) e[f % 13] = EMB_LD(f + 13);
        int b = f * 32 + lane;
        float2 c;
        c = sv0[b]; acc0 += ev.x * c.x + ev.y * c.y;
        c = sv1[b]; acc1 += ev.x * c.x + ev.y * c.y;
        c = sv2[b]; acc2 += ev.x * c.x + ev.y * c.y;
        c = sv3[b]; acc3 += ev.x * c.x + ev.y * c.y;
        c = sv4[b]; acc4 += ev.x * c.x + ev.y * c.y;
    }
    #undef EMB_LD

    if (lane < NUMB) acc4 += numb[row * NUMB + lane] * s_qn[lane];

    acc0 = warp_sum(acc0);
    acc1 = warp_sum(acc1);
    acc2 = warp_sum(acc2);
    acc3 = warp_sum(acc3);
    acc4 = warp_sum(acc4);

    if (lane == 0) {
        float cb0 = cross_b[0], cb1 = cross_b[1], cb2 = cross_b[2];
        float Sc1 = s_sc[0], Sc2 = s_sc[1], Sp = s_sc[2], rtot = s_sc[3];

        float al = acc0 + 1.f;
        float be = cb0;
        float sd1 = al * acc1 + be * Sc1;
        al = (sd1 + 1.f) * al;
        be = (sd1 + 1.f) * be + cb1;
        float sd2 = al * acc2 + be * Sc2;
        al = (sd2 + 1.f) * al;
        be = (sd2 + 1.f) * be + cb2;

        float z = al * acc3 + be * Sp + acc4 + rtot;
        out[row] = 1.f / (1.f + expf(-z));
    }
}

// ---------------------------------------------------------------------------
extern "C" void kernel_launch(void* const* d_in, const int* in_sizes, int n_in,
                              void* d_out, int out_size) {
    const float* numb    = (const float*)d_in[0];
    const int*   cat     = (const int*)  d_in[1];
    const float* emb     = (const float*)d_in[2];
    const float* bn0     = (const float*)d_in[3];
    const float* w1      = (const float*)d_in[4];
    const float* b1      = (const float*)d_in[5];
    const float* bn1     = (const float*)d_in[6];
    const float* w2      = (const float*)d_in[7];
    const float* b2      = (const float*)d_in[8];
    const float* bn2     = (const float*)d_in[9];
    const float* w3      = (const float*)d_in[10];
    const float* b3      = (const float*)d_in[11];
    const float* bn3     = (const float*)d_in[12];
    const float* cross_w = (const float*)d_in[13];
    const float* cross_b = (const float*)d_in[14];
    const float* pred_w  = (const float*)d_in[15];
    const float* pred_b  = (const float*)d_in[16];
    float* out = (float*)d_out;

    k_v3<<<32, 256>>>(w3, bn3, pred_w, pred_b);
    k_v2<<<128, 128>>>(w2, bn2, b2, bn3, b3, pred_w);
    k_u<<<112, 256>>>(w1, bn1, b1, bn0);
    k_main<<<256, 512>>>(numb, cat, emb, cross_w, cross_b, pred_w, bn0, out);
}

// round 8
// speedup vs baseline: 1.1064x; 1.1064x over previous
#include <cuda_runtime.h>
#include <math.h>

// DCN collapsed-affine, round 8:
//  - k_main: 256 thr (8 warps), 2 rows/warp, grid 256, float4 + 2-features-
//    per-LDG gather, depth-3 register prefetch. LDS bytes/row halved, LDG/LDS
//    instruction count halved/quartered.
//  - chain: k_u widened to 224 blocks.

#define EPSF 1e-5f

constexpr int Bn   = 4096;
constexpr int Fn   = 26;
constexpr int Vn   = 10000;
constexpr int Dn   = 64;
constexpr int D0   = 1664;   // Fn*Dn
constexpr int NUMB = 13;
constexpr int INW  = 1677;   // D0 + NUMB
constexpr int H1   = 1024;
constexpr int H2   = 512;
constexpr int H3   = 256;

// Scratch (device globals)
__device__ float g_v3p[16][H2];
__device__ float g_v2p[16][H1];
__device__ float g_u[1792];
__device__ float g_r;

__device__ __forceinline__ float warp_sum(float v) {
    #pragma unroll
    for (int o = 16; o; o >>= 1) v += __shfl_xor_sync(0xffffffffu, v, o);
    return v;
}

// ---------------------------------------------------------------------------
__global__ __launch_bounds__(256) void k_v3(
    const float* __restrict__ w3, const float* __restrict__ bn3,
    const float* __restrict__ pred_w, const float* __restrict__ pred_b) {
    int bid = blockIdx.x;
    int ib = bid >> 1, jb = bid & 1;
    int t = threadIdx.x;
    int i0 = ib * 16;
    __shared__ float ts[16];
    if (t < 16) {
        int i = i0 + t;
        float a3 = bn3[i] * rsqrtf(bn3[3 * H3 + i] + EPSF);
        ts[t] = a3 * pred_w[D0 + i];
    }
    int gt = bid * 256 + t;
    if (gt < 1792) g_u[gt] = 0.f;
    if (gt == 0) g_r = pred_b[0];
    __syncthreads();
    int j = jb * 256 + t;
    float acc = 0.f;
    #pragma unroll
    for (int i = 0; i < 16; i++) acc += w3[(i0 + i) * H2 + j] * ts[i];
    g_v3p[ib][j] = acc;
}

// ---------------------------------------------------------------------------
__global__ __launch_bounds__(128) void k_v2(
    const float* __restrict__ w2, const float* __restrict__ bn2,
    const float* __restrict__ b2, const float* __restrict__ bn3,
    const float* __restrict__ b3, const float* __restrict__ pred_w) {
    int bid = blockIdx.x;
    int jb = bid & 7, ib = bid >> 3;
    int t = threadIdx.x;
    int i0 = ib * 32;
    __shared__ float ts[32];
    __shared__ float red[4];
    float rloc = 0.f;

    if (t < 32) {
        int i = i0 + t;
        float v3 = 0.f;
        #pragma unroll
        for (int p = 0; p < 16; p++) v3 += g_v3p[p][i];
        float a2 = bn2[i] * rsqrtf(bn2[3 * H2 + i] + EPSF);
        ts[t] = a2 * v3;
        if (jb == 0)
            rloc += (a2 * b2[i] + bn2[H2 + i] - bn2[2 * H2 + i] * a2) * v3;
    }
    if (bid == 0) {
        #pragma unroll
        for (int i = t; i < H3; i += 128) {
            float a3 = bn3[i] * rsqrtf(bn3[3 * H3 + i] + EPSF);
            rloc += (a3 * b3[i] + bn3[H3 + i] - bn3[2 * H3 + i] * a3) * pred_w[D0 + i];
        }
    }
    __syncthreads();

    int j = jb * 128 + t;
    float acc = 0.f;
    #pragma unroll 8
    for (int i = 0; i < 32; i++) acc += w2[(i0 + i) * H1 + j] * ts[i];
    g_v2p[ib][j] = acc;

    if (jb == 0) {
        rloc = warp_sum(rloc);
        if ((t & 31) == 0) red[t >> 5] = rloc;
        __syncthreads();
        if (t == 0) atomicAdd(&g_r, red[0] + red[1] + red[2] + red[3]);
    }
}

// ---------------------------------------------------------------------------
// u: grid 224 = ib(32, chunk 32) x jb(7, 256 cols), block 256.
__global__ __launch_bounds__(256) void k_u(
    const float* __restrict__ w1, const float* __restrict__ bn1,
    const float* __restrict__ b1, const float* __restrict__ bn0) {
    int bid = blockIdx.x;
    int jb = bid % 7, ib = bid / 7;
    int t = threadIdx.x;
    int i0 = ib * 32;
    __shared__ float ts[32];
    __shared__ float red[8];
    float rloc = 0.f;

    if (t < 32) {
        int i = i0 + t;
        float v2 = 0.f;
        #pragma unroll
        for (int p = 0; p < 16; p++) v2 += g_v2p[p][i];
        float a1 = bn1[i] * rsqrtf(bn1[3 * H1 + i] + EPSF);
        ts[t] = a1 * v2;
        if (jb == 0)
            rloc += (a1 * b1[i] + bn1[H1 + i] - bn1[2 * H1 + i] * a1) * v2;
    }
    __syncthreads();

    int j = jb * 256 + t;
    if (j < INW) {
        float acc = 0.f;
        #pragma unroll 8
        for (int i = 0; i < 32; i++)
            acc += w1[(size_t)(i0 + i) * INW + j] * ts[i];
        atomicAdd(&g_u[j], acc);
        float a0 = bn0[j] * rsqrtf(bn0[3 * INW + j] + EPSF);
        float c0 = bn0[INW + j] - bn0[2 * INW + j] * a0;
        rloc += c0 * acc;
    }

    rloc = warp_sum(rloc);
    if ((t & 31) == 0) red[t >> 5] = rloc;
    __syncthreads();
    if (t == 0) {
        float rb = 0.f;
        #pragma unroll
        for (int w = 0; w < 8; w++) rb += red[w];
        atomicAdd(&g_r, rb);
    }
}

// ---------------------------------------------------------------------------
// Main gather kernel: 256 thr (8 warps), 2 rows/warp, grid 256, 3 blocks/SM.
// float4 loads, 2 features per LDG (lanes 0-15: feature 2f, 16-31: 2f+1),
// depth-3 prefetch on both rows.
__global__ __launch_bounds__(256, 3) void k_main(
    const float* __restrict__ numb, const int* __restrict__ cat,
    const float* __restrict__ emb,  const float* __restrict__ cross_w,
    const float* __restrict__ cross_b, const float* __restrict__ pred_w,
    const float* __restrict__ bn0, float* __restrict__ out) {

    __shared__ float4 sv[5][416];    // cw0, cw1, cw2, pw_x, q_x (1664 floats each)
    __shared__ float  s_qn[16];
    __shared__ float  redm[3][8];
    __shared__ float  s_sc[4];

    const int tid  = threadIdx.x;
    const int warp = tid >> 5;
    const int lane = tid & 31;
    const int sub  = lane & 15;
    const int fsel = lane >> 4;      // 0 or 1: which feature of the pair
    const int rowA = blockIdx.x * 16 + warp * 2;
    const int rowB = rowA + 1;

    int miA = (lane < Fn) ? cat[rowA * Fn + lane] : 0;
    int miB = (lane < Fn) ? cat[rowB * Fn + lane] : 0;

    // ---- prologue: stage coefficients (float4), q from g_u, Sc sums ----
    float p1 = 0.f, p2 = 0.f, p3 = 0.f;
    {
        const float4* cwp = (const float4*)cross_w;   // 3 x 416 float4
        const float4* pwp = (const float4*)pred_w;    // 480 float4 (first 416 = x)
        #pragma unroll
        for (int k = tid; k < 416; k += 256) {
            float4 c0 = cwp[k];
            float4 c1 = cwp[416 + k];
            float4 c2 = cwp[832 + k];
            float4 pw = pwp[k];
            sv[0][k] = c0; sv[1][k] = c1; sv[2][k] = c2; sv[3][k] = pw;
            p1 += (c1.x + c1.y) + (c1.z + c1.w);
            p2 += (c2.x + c2.y) + (c2.z + c2.w);
            p3 += (pw.x + pw.y) + (pw.z + pw.w);
        }
        float* sv4f = (float*)sv[4];
        #pragma unroll
        for (int j = tid; j < INW; j += 256) {
            float a0 = bn0[j] * rsqrtf(bn0[3 * INW + j] + EPSF);
            float q = a0 * g_u[j];
            if (j < D0) sv4f[j] = q;
            else        s_qn[j - D0] = q;
        }
        if (tid == 0) s_sc[3] = g_r;
    }
    p1 = warp_sum(p1); p2 = warp_sum(p2); p3 = warp_sum(p3);
    if (lane == 0) { redm[0][warp] = p1; redm[1][warp] = p2; redm[2][warp] = p3; }
    __syncthreads();
    if (tid < 32) {
        float a = (tid < 8) ? redm[0][tid] : 0.f;
        float b = (tid < 8) ? redm[1][tid] : 0.f;
        float c = (tid < 8) ? redm[2][tid] : 0.f;
        a = warp_sum(a); b = warp_sum(b); c = warp_sum(c);
        if (tid == 0) { s_sc[0] = a; s_sc[1] = b; s_sc[2] = c; }
    }
    __syncthreads();

    // ---- gather: 13 feature-pair iterations, 2 rows, depth-3 prefetch ----
    float a0A = 0.f, a1A = 0.f, a2A = 0.f, a3A = 0.f, a4A = 0.f;
    float a0B = 0.f, a1B = 0.f, a2B = 0.f, a3B = 0.f, a4B = 0.f;

    #define EMB_LD(MI, FP) \
        __ldg(reinterpret_cast<const float4*>(emb + (size_t)(2*(FP)+fsel) * (Vn*Dn)) \
              + (size_t)__shfl_sync(0xffffffffu, (MI), 2*(FP)+fsel) * 16 + sub)

    float4 eA[3], eB[3];
    #pragma unroll
    for (int d = 0; d < 3; d++) { eA[d] = EMB_LD(miA, d); eB[d] = EMB_LD(miB, d); }

    #pragma unroll
    for (int fp = 0; fp < 13; fp++) {
        float4 evA = eA[fp % 3];
        float4 evB = eB[fp % 3];
        if (fp + 3 < 13) {
            eA[fp % 3] = EMB_LD(miA, fp + 3);
            eB[fp % 3] = EMB_LD(miB, fp + 3);
        }
        int ci = (2 * fp + fsel) * 16 + sub;
        float4 c;
        c = sv[0][ci];
        a0A += evA.x*c.x + evA.y*c.y + evA.z*c.z + evA.w*c.w;
        a0B += evB.x*c.x + evB.y*c.y + evB.z*c.z + evB.w*c.w;
        c = sv[1][ci];
        a1A += evA.x*c.x + evA.y*c.y + evA.z*c.z + evA.w*c.w;
        a1B += evB.x*c.x + evB.y*c.y + evB.z*c.z + evB.w*c.w;
        c = sv[2][ci];
        a2A += evA.x*c.x + evA.y*c.y + evA.z*c.z + evA.w*c.w;
        a2B += evB.x*c.x + evB.y*c.y + evB.z*c.z + evB.w*c.w;
        c = sv[3][ci];
        a3A += evA.x*c.x + evA.y*c.y + evA.z*c.z + evA.w*c.w;
        a3B += evB.x*c.x + evB.y*c.y + evB.z*c.z + evB.w*c.w;
        c = sv[4][ci];
        a4A += evA.x*c.x + evA.y*c.y + evA.z*c.z + evA.w*c.w;
        a4B += evB.x*c.x + evB.y*c.y + evB.z*c.z + evB.w*c.w;
    }
    #undef EMB_LD

    if (lane < NUMB)
        a4A += numb[rowA * NUMB + lane] * s_qn[lane];
    else if (lane >= 16 && lane < 16 + NUMB)
        a4B += numb[rowB * NUMB + (lane - 16)] * s_qn[lane - 16];

    a0A = warp_sum(a0A); a1A = warp_sum(a1A); a2A = warp_sum(a2A);
    a3A = warp_sum(a3A); a4A = warp_sum(a4A);
    a0B = warp_sum(a0B); a1B = warp_sum(a1B); a2B = warp_sum(a2B);
    a3B = warp_sum(a3B); a4B = warp_sum(a4B);

    if (lane < 2) {
        float d0 = (lane == 0) ? a0A : a0B;
        float d1 = (lane == 0) ? a1A : a1B;
        float d2 = (lane == 0) ? a2A : a2B;
        float d3 = (lane == 0) ? a3A : a3B;
        float d4 = (lane == 0) ? a4A : a4B;
        int   rw = (lane == 0) ? rowA : rowB;

        float cb0 = cross_b[0], cb1 = cross_b[1], cb2 = cross_b[2];
        float Sc1 = s_sc[0], Sc2 = s_sc[1], Sp = s_sc[2], rtot = s_sc[3];

        float al = d0 + 1.f;
        float be = cb0;
        float sd1 = al * d1 + be * Sc1;
        al = (sd1 + 1.f) * al;
        be = (sd1 + 1.f) * be + cb1;
        float sd2 = al * d2 + be * Sc2;
        al = (sd2 + 1.f) * al;
        be = (sd2 + 1.f) * be + cb2;

        float z = al * d3 + be * Sp + d4 + rtot;
        out[rw] = 1.f / (1.f + expf(-z));
    }
}

// ---------------------------------------------------------------------------
extern "C" void kernel_launch(void* const* d_in, const int* in_sizes, int n_in,
                              void* d_out, int out_size) {
    const float* numb    = (const float*)d_in[0];
    const int*   cat     = (const int*)  d_in[1];
    const float* emb     = (const float*)d_in[2];
    const float* bn0     = (const float*)d_in[3];
    const float* w1      = (const float*)d_in[4];
    const float* b1      = (const float*)d_in[5];
    const float* bn1     = (const float*)d_in[6];
    const float* w2      = (const float*)d_in[7];
    const float* b2      = (const float*)d_in[8];
    const float* bn2     = (const float*)d_in[9];
    const float* w3      = (const float*)d_in[10];
    const float* b3      = (const float*)d_in[11];
    const float* bn3     = (const float*)d_in[12];
    const float* cross_w = (const float*)d_in[13];
    const float* cross_b = (const float*)d_in[14];
    const float* pred_w  = (const float*)d_in[15];
    const float* pred_b  = (const float*)d_in[16];
    float* out = (float*)d_out;

    k_v3<<<32, 256>>>(w3, bn3, pred_w, pred_b);
    k_v2<<<128, 128>>>(w2, bn2, b2, bn3, b3, pred_w);
    k_u<<<224, 256>>>(w1, bn1, b1, bn0);
    k_main<<<256, 256>>>(numb, cat, emb, cross_w, cross_b, pred_w, bn0, out);
}